// round 11
// baseline (speedup 1.0000x reference)
#include <cuda_runtime.h>
#include <cuda_bf16.h>

#define BB 16
#define NN 4096
#define DD 256
#define BN (BB * NN)
#define EPSF 1e-6f
#define KSPL 4
#define NKV (NN / KSPL)

#define TILE_U16 (128 * 72)                 // one tile: 128 rows x 72 u16 (64 data + 8 pad)
#define TILE_B (TILE_U16 * 2)               // 18432 bytes
#define STAGE_B (3 * TILE_B)                // Ah, Bh, Bl = 55296 bytes
#define SMEM_BYTES (2 * STAGE_B)            // 110592 bytes (2 stages)

typedef unsigned short u16;
typedef unsigned int u32;

// ---------------- scratch (device globals; allocation-free) ----------------
__device__ __align__(128) u16 g_q_h[(size_t)BN * DD];                  // Q hi [n,k]
__device__ __align__(128) u16 g_k_h[(size_t)BN * DD], g_k_l[(size_t)BN * DD]; // K hi/lo [n,k]
__device__ __align__(128) u16 g_wqt_h[DD * DD], g_wqt_l[DD * DD];      // WqT [e,k]
__device__ __align__(128) u16 g_wkt_h[DD * DD];                        // WkT [e,k] hi
__device__ __align__(128) u16 g_phiq_h[(size_t)BN * DD];               // [n,e] hi
__device__ __align__(128) u16 g_phikt_h[(size_t)BN * DD], g_phikt_l[(size_t)BN * DD]; // [b,e,n]
__device__ __align__(128) u16 g_e_h[(size_t)BN * DD];                  // E^T [b,e,n] hi
__device__ float g_vt[(size_t)BN * DD];                                // V^T [b,e,n]
__device__ float g_sm[BB * DD];                                        // softmax denoms
__device__ float g_rs[BB * NN];                                        // phi_q row sums
__device__ float g_kvp[(size_t)KSPL * BB * DD * DD];                   // partial KV^T
__device__ __align__(128) u16 g_kvt_h[(size_t)BB * DD * DD], g_kvt_l[(size_t)BB * DD * DD];

// ---------------- helpers ----------------
__device__ __forceinline__ float sigmoidf_(float x) { return 1.f / (1.f + __expf(-x)); }

__device__ __forceinline__ u32 smem_u32(const void* p) {
    u32 a;
    asm("{ .reg .u64 t; cvta.to.shared.u64 t, %1; cvt.u32.u64 %0, t; }" : "=r"(a) : "l"(p));
    return a;
}

__device__ __forceinline__ void cvt2(float x, float y, u32& ho, u32& lo) {
    __nv_bfloat162 h = __floats2bfloat162_rn(x, y);
    float2 hf = __bfloat1622float2(h);
    __nv_bfloat162 l = __floats2bfloat162_rn(x - hf.x, y - hf.y);
    ho = *(u32*)&h; lo = *(u32*)&l;
}

__device__ __forceinline__ void store_hl(u16* ph, u16* pl, size_t idx, float v0, float v1) {
    u32 h, l;
    cvt2(v0, v1, h, l);
    *(u32*)(ph + idx) = h;
    *(u32*)(pl + idx) = l;
}

__device__ __forceinline__ void store_h(u16* ph, size_t idx, float v0, float v1) {
    __nv_bfloat162 h = __floats2bfloat162_rn(v0, v1);
    *(u32*)(ph + idx) = *(u32*)&h;
}

#define MMA16816(cc, aa, b0, b1)                                               \
    asm volatile("mma.sync.aligned.m16n8k16.row.col.f32.bf16.bf16.f32 "        \
                 "{%0,%1,%2,%3}, {%4,%5,%6,%7}, {%8,%9}, {%0,%1,%2,%3};"       \
                 : "+f"((cc)[0]), "+f"((cc)[1]), "+f"((cc)[2]), "+f"((cc)[3])  \
                 : "r"((aa)[0]), "r"((aa)[1]), "r"((aa)[2]), "r"((aa)[3]),     \
                   "r"(b0), "r"(b1))

#define LDSM4(rr, addr)                                                        \
    asm volatile("ldmatrix.sync.aligned.m8n8.x4.shared.b16 {%0,%1,%2,%3}, [%4];" \
                 : "=r"((rr)[0]), "=r"((rr)[1]), "=r"((rr)[2]), "=r"((rr)[3])  \
                 : "r"(addr))

#define MMAALL(AF, BF)                                                         \
    _Pragma("unroll") for (int mi = 0; mi < 4; mi++)                           \
    _Pragma("unroll") for (int nj = 0; nj < 4; nj++)                           \
        MMA16816(c[mi][nj], AF[mi], BF[nj >> 1][nj & 1], BF[nj >> 1][(nj & 1) + 2]);

// ---- cp.async: one tile = 128 rows x 64 u16 (128B) into 144B-stride smem ----
__device__ __forceinline__ void cpa_tile(u32 sdst, const u16* __restrict__ g,
                                         size_t ldg, int tid) {
#pragma unroll
    for (int i = 0; i < 4; i++) {
        int id = tid + 256 * i;          // 0..1023
        int row = id >> 3, seg = id & 7; // 128 rows x 8 segs of 16B
        const void* src = g + (size_t)row * ldg + seg * 8;
        u32 dst = sdst + row * 144 + seg * 16;
        asm volatile("cp.async.cg.shared.global [%0], [%1], 16;" :: "r"(dst), "l"(src));
    }
}

// ---------------------------------------------------------------------------
// Double-buffered GEMM core: 128x128 tile, 8 warps (2m x 4n), warp 64x32,
// K staged by 64, 2-term split (Ah*Bh + Ah*Bl), fp32 accum.
// cp.async prefetch of chunk i+1 overlaps compute of chunk i; second barrier
// after compute guards the stage against overwrite (the R8 race, fixed).
// ---------------------------------------------------------------------------
#define GEMM_PIPE(KTOT, gA, lda, gBh, gBl, ldb)                                \
    extern __shared__ u16 smemu[];                                             \
    const u32 sbase = smem_u32(smemu);                                         \
    float c[4][4][4];                                                          \
    _Pragma("unroll") for (int i_ = 0; i_ < 4; i_++)                           \
    _Pragma("unroll") for (int j_ = 0; j_ < 4; j_++)                           \
    _Pragma("unroll") for (int r_ = 0; r_ < 4; r_++) c[i_][j_][r_] = 0.f;      \
    const int lane = tid & 31, widx = tid >> 5;                                \
    const int wm = widx >> 2, wn = widx & 3;                                   \
    const u32 frow = (u32)(lane & 15) * 144 + (u32)(lane >> 4) * 16;           \
    cpa_tile(sbase,              (gA),  (lda), tid);                           \
    cpa_tile(sbase + TILE_B,     (gBh), (ldb), tid);                           \
    cpa_tile(sbase + 2 * TILE_B, (gBl), (ldb), tid);                           \
    asm volatile("cp.async.commit_group;" ::: "memory");                       \
    const int nch = (KTOT) >> 6;                                               \
    for (int ci = 0; ci < nch; ci++) {                                         \
        if (ci + 1 < nch) {                                                    \
            u32 st = sbase + ((ci + 1) & 1) * STAGE_B;                         \
            int kk = (ci + 1) << 6;                                            \
            cpa_tile(st,              (gA) + kk,  (lda), tid);                 \
            cpa_tile(st + TILE_B,     (gBh) + kk, (ldb), tid);                 \
            cpa_tile(st + 2 * TILE_B, (gBl) + kk, (ldb), tid);                 \
            asm volatile("cp.async.commit_group;" ::: "memory");               \
            asm volatile("cp.async.wait_group 1;" ::: "memory");               \
        } else {                                                               \
            asm volatile("cp.async.wait_group 0;" ::: "memory");               \
        }                                                                      \
        __syncthreads();                                                       \
        u32 sb  = sbase + (ci & 1) * STAGE_B;                                  \
        u32 uAh = sb + wm * 64 * 144 + frow;                                   \
        u32 uBh = sb + TILE_B + wn * 32 * 144 + frow;                          \
        u32 uBl = uBh + TILE_B;                                                \
        _Pragma("unroll")                                                      \
        for (int s = 0; s < 4; s++) {                                          \
            u32 ah[4][4], bb[2][4];                                            \
            LDSM4(bb[0], uBh + s * 32);                                        \
            LDSM4(bb[1], uBh + 16 * 144 + s * 32);                             \
            _Pragma("unroll") for (int mi = 0; mi < 4; mi++)                   \
                LDSM4(ah[mi], uAh + mi * 16 * 144 + s * 32);                   \
            MMAALL(ah, bb)                                                     \
            LDSM4(bb[0], uBl + s * 32);                                        \
            LDSM4(bb[1], uBl + 16 * 144 + s * 32);                             \
            MMAALL(ah, bb)                                                     \
        }                                                                      \
        __syncthreads();                                                       \
    }

// epilogue loop; variadic so bodies may contain top-level commas
#define EPILOOP(...)                                                           \
    _Pragma("unroll") for (int mi = 0; mi < 4; mi++)                           \
    _Pragma("unroll") for (int nj = 0; nj < 4; nj++) {                         \
        int r0 = wm * 64 + mi * 16 + (lane >> 2);                              \
        int cc0 = wn * 32 + nj * 8 + ((lane & 3) << 1);                        \
        __VA_ARGS__                                                            \
    }

// ---------------------------------------------------------------------------
// prepasses
// ---------------------------------------------------------------------------
__global__ void __launch_bounds__(256)
k_cvt_hi(const float* __restrict__ X, u16* __restrict__ xh)
{
    size_t i = ((size_t)blockIdx.x * 256 + threadIdx.x) * 8;
    float4 a = *(const float4*)(X + i);
    float4 b = *(const float4*)(X + i + 4);
    __nv_bfloat162 h0 = __floats2bfloat162_rn(a.x, a.y);
    __nv_bfloat162 h1 = __floats2bfloat162_rn(a.z, a.w);
    __nv_bfloat162 h2 = __floats2bfloat162_rn(b.x, b.y);
    __nv_bfloat162 h3 = __floats2bfloat162_rn(b.z, b.w);
    uint4 H = make_uint4(*(u32*)&h0, *(u32*)&h1, *(u32*)&h2, *(u32*)&h3);
    *(uint4*)(xh + i) = H;
}

__global__ void __launch_bounds__(256)
k_cvt_hl(const float* __restrict__ X, u16* __restrict__ xh, u16* __restrict__ xl)
{
    size_t i = ((size_t)blockIdx.x * 256 + threadIdx.x) * 8;
    float4 a = *(const float4*)(X + i);
    float4 b = *(const float4*)(X + i + 4);
    u32 H[4], L[4];
    cvt2(a.x, a.y, H[0], L[0]); cvt2(a.z, a.w, H[1], L[1]);
    cvt2(b.x, b.y, H[2], L[2]); cvt2(b.z, b.w, H[3], L[3]);
    *(uint4*)(xh + i) = *(uint4*)H;
    *(uint4*)(xl + i) = *(uint4*)L;
}

__global__ void k_wprep(const float* __restrict__ Wq, const float* __restrict__ Wk)
{
    int e = blockIdx.x, k = threadIdx.x;
    float q = Wq[(size_t)k * DD + e];
    float kk = Wk[(size_t)k * DD + e];
    __nv_bfloat16 qh = __float2bfloat16(q);
    __nv_bfloat16 ql = __float2bfloat16(q - __bfloat162float(qh));
    __nv_bfloat16 kh = __float2bfloat16(kk);
    g_wqt_h[e * DD + k] = *(u16*)&qh;  g_wqt_l[e * DD + k] = *(u16*)&ql;
    g_wkt_h[e * DD + k] = *(u16*)&kh;
}

// V transpose: V[b,n,e] -> V^T[b,e,n]
__global__ void k_transV(const float* __restrict__ V)
{
    __shared__ float t[32][33];
    int n0 = blockIdx.x * 32, e0 = blockIdx.y * 32, b = blockIdx.z;
    int tx = threadIdx.x, ty = threadIdx.y;
#pragma unroll
    for (int i = 0; i < 4; i++)
        t[ty + 8 * i][tx] = V[((size_t)b * NN + n0 + ty + 8 * i) * DD + e0 + tx];
    __syncthreads();
#pragma unroll
    for (int i = 0; i < 4; i++)
        g_vt[((size_t)b * DD + e0 + ty + 8 * i) * NN + n0 + tx] = t[tx][ty + 8 * i];
}

// ---------------------------------------------------------------------------
// phi_q[n,e] = sigmoid(Q@Wq + bq).  A=Q hi [n,k], B=WqT hi+lo [e,k]
// ---------------------------------------------------------------------------
__global__ void __launch_bounds__(256, 2)
k_phiq(const float* __restrict__ bq)
{
    const int tid = threadIdx.x;
    const int m0 = blockIdx.x * 128;   // global n
    const int e0 = blockIdx.y * 128;

    GEMM_PIPE(DD, g_q_h + (size_t)m0 * DD, DD,
              g_wqt_h + (size_t)e0 * DD, g_wqt_l + (size_t)e0 * DD, DD)

    EPILOOP(
        int e = e0 + cc0;
        float2 bqe = *(const float2*)(bq + e);
        int n0g = m0 + r0;
        store_h(g_phiq_h, (size_t)n0g * DD + e,
                sigmoidf_(c[mi][nj][0] + bqe.x), sigmoidf_(c[mi][nj][1] + bqe.y));
        store_h(g_phiq_h, (size_t)(n0g + 8) * DD + e,
                sigmoidf_(c[mi][nj][2] + bqe.x), sigmoidf_(c[mi][nj][3] + bqe.y));
    )
}

// ---------------------------------------------------------------------------
// phi_k^T[b,e,n] = sigmoid(K@Wk + bk)^T.  A=WkT hi [e,k], B=K hi+lo [n,k]
// ---------------------------------------------------------------------------
__global__ void __launch_bounds__(256, 2)
k_phik(const float* __restrict__ bk)
{
    const int tid = threadIdx.x;
    const int n0 = blockIdx.x * 128;   // global n
    const int m0e = blockIdx.y * 128;  // e

    GEMM_PIPE(DD, g_wkt_h + (size_t)m0e * DD, DD,
              g_k_h + (size_t)n0 * DD, g_k_l + (size_t)n0 * DD, DD)

    EPILOOP(
        int er = m0e + r0;
        int gn = n0 + cc0;
        int b = gn >> 12;
        int nl = gn & (NN - 1);
        float b0 = bk[er];
        float b1 = bk[er + 8];
        store_hl(g_phikt_h, g_phikt_l, ((size_t)b * DD + er) * NN + nl,
                 sigmoidf_(c[mi][nj][0] + b0), sigmoidf_(c[mi][nj][1] + b0));
        store_hl(g_phikt_h, g_phikt_l, ((size_t)b * DD + er + 8) * NN + nl,
                 sigmoidf_(c[mi][nj][2] + b1), sigmoidf_(c[mi][nj][3] + b1));
    )
}

// ---------------------------------------------------------------------------
// per (b,e): colsum(phi_k) -> inv; E = exp(phi_k*V*inv); rowsum(E) -> sm
// ---------------------------------------------------------------------------
__global__ void __launch_bounds__(256) k_cs_exp()
{
    __shared__ float red[256];
    const int e = blockIdx.x, b = blockIdx.y, tid = threadIdx.x;
    const size_t base = ((size_t)b * DD + e) * NN;
    const u16* ph = g_phikt_h + base;
    const u16* pl = g_phikt_l + base;
    const float* vt = g_vt + base;

    float pkx[8], pky[8];
    float s = 0.f;
#pragma unroll
    for (int i = 0; i < 8; i++) {
        int n = i * 512 + tid * 2;
        u32 hp = *(const u32*)(ph + n);
        u32 lp = *(const u32*)(pl + n);
        float2 hf = __bfloat1622float2(*(__nv_bfloat162*)&hp);
        float2 lf = __bfloat1622float2(*(__nv_bfloat162*)&lp);
        pkx[i] = hf.x + lf.x;
        pky[i] = hf.y + lf.y;
        s += pkx[i] + pky[i];
    }
    red[tid] = s; __syncthreads();
    for (int o = 128; o > 0; o >>= 1) { if (tid < o) red[tid] += red[tid + o]; __syncthreads(); }
    const float inv = 1.f / (red[0] + EPSF);
    __syncthreads();

    float s2 = 0.f;
#pragma unroll
    for (int i = 0; i < 8; i++) {
        int n = i * 512 + tid * 2;
        float2 vv = *(const float2*)(vt + n);
        float E0 = __expf(pkx[i] * vv.x * inv);
        float E1 = __expf(pky[i] * vv.y * inv);
        store_h(g_e_h, base + n, E0, E1);
        s2 += E0 + E1;
    }
    red[tid] = s2; __syncthreads();
    for (int o = 128; o > 0; o >>= 1) { if (tid < o) red[tid] += red[tid + o]; __syncthreads(); }
    if (tid == 0) g_sm[b * DD + e] = red[0];
}

// row sums of phi_q over d (warp per row, hi plane only)
__global__ void __launch_bounds__(256) k_rowsum()
{
    const int row = blockIdx.x * 8 + (threadIdx.x >> 5);
    const int lane = threadIdx.x & 31;
    const u16* ph = g_phiq_h + (size_t)row * DD;
    float s = 0.f;
#pragma unroll
    for (int i = 0; i < 4; i++) {
        int j2 = (lane + 32 * i) * 2;
        u32 hp = *(const u32*)(ph + j2);
        float2 hf = __bfloat1622float2(*(__nv_bfloat162*)&hp);
        s += hf.x + hf.y;
    }
#pragma unroll
    for (int o = 16; o > 0; o >>= 1) s += __shfl_down_sync(0xffffffffu, s, o);
    if (lane == 0) g_rs[row] = s;
}

// ---------------------------------------------------------------------------
// KV partial: kvp[spl,b,e,d] = sum_{n in slice} E^T[e,n]*phi_k^T[d,n]
// A=E^T hi, B=phi_k^T hi+lo
// ---------------------------------------------------------------------------
__global__ void __launch_bounds__(256, 2) k_kv()
{
    const int tid = threadIdx.x;
    const int d0 = blockIdx.x * 128;
    const int e0 = blockIdx.y * 128;
    const int b = blockIdx.z >> 2;
    const int spl = blockIdx.z & 3;
    const size_t abase = ((size_t)b * DD + e0) * NN + spl * NKV;
    const size_t bbase = ((size_t)b * DD + d0) * NN + spl * NKV;

    GEMM_PIPE(NKV, g_e_h + abase, NN, g_phikt_h + bbase, g_phikt_l + bbase, NN)

    float* dst = g_kvp + (size_t)(spl * BB + b) * DD * DD;
    EPILOOP(
        int e = e0 + r0;
        int d = d0 + cc0;
        *(float2*)(dst + (size_t)e * DD + d) = make_float2(c[mi][nj][0], c[mi][nj][1]);
        *(float2*)(dst + (size_t)(e + 8) * DD + d) = make_float2(c[mi][nj][2], c[mi][nj][3]);
    )
}

// merge split-K, divide by sm[b,e], split-store KV^T [b,e,d]
__global__ void __launch_bounds__(256) k_kvmerge()
{
    const size_t idx = (size_t)blockIdx.x * 256 + threadIdx.x;
    const size_t S = (size_t)BB * DD * DD;
    const int e = (int)((idx >> 8) & 255);
    const int b = (int)(idx >> 16);
    float s = g_kvp[idx] + g_kvp[S + idx] + g_kvp[2 * S + idx] + g_kvp[3 * S + idx];
    float v = s / g_sm[b * DD + e];
    __nv_bfloat16 h = __float2bfloat16(v);
    __nv_bfloat16 l = __float2bfloat16(v - __bfloat162float(h));
    g_kvt_h[idx] = *(u16*)&h;
    g_kvt_l[idx] = *(u16*)&l;
}

// ---------------------------------------------------------------------------
// out[n,e] = sigmoid(rs)/(rs+eps) * sum_d phi_q[n,d]*KV^T[e,d]
// A=phi_q hi, B=KV^T hi+lo
// ---------------------------------------------------------------------------
__global__ void __launch_bounds__(256, 2) k_out(float* __restrict__ out)
{
    const int tid = threadIdx.x;
    const int m0 = blockIdx.x * 128;   // global n
    const int e0 = blockIdx.y * 128;
    const int b = m0 >> 12;
    const size_t abase = (size_t)m0 * DD;
    const size_t bbase = ((size_t)b * DD + e0) * DD;

    GEMM_PIPE(DD, g_phiq_h + abase, DD, g_kvt_h + bbase, g_kvt_l + bbase, DD)

    EPILOOP(
        int ng = m0 + r0;
        int e = e0 + cc0;
        float rs0 = g_rs[ng];
        float rs1 = g_rs[ng + 8];
        float s0 = sigmoidf_(rs0) / (rs0 + EPSF);
        float s1 = sigmoidf_(rs1) / (rs1 + EPSF);
        *(float2*)(out + (size_t)ng * DD + e) =
            make_float2(c[mi][nj][0] * s0, c[mi][nj][1] * s0);
        *(float2*)(out + (size_t)(ng + 8) * DD + e) =
            make_float2(c[mi][nj][2] * s1, c[mi][nj][3] * s1);
    )
}

// ---------------------------------------------------------------------------
extern "C" void kernel_launch(void* const* d_in, const int* in_sizes, int n_in,
                              void* d_out, int out_size)
{
    const float* Q  = (const float*)d_in[0];
    const float* K  = (const float*)d_in[1];
    const float* V  = (const float*)d_in[2];
    const float* Wq = (const float*)d_in[3];
    const float* bq = (const float*)d_in[4];
    const float* Wk = (const float*)d_in[5];
    const float* bk = (const float*)d_in[6];
    float* out = (float*)d_out;

    cudaFuncSetAttribute(k_phiq, cudaFuncAttributeMaxDynamicSharedMemorySize, SMEM_BYTES);
    cudaFuncSetAttribute(k_phik, cudaFuncAttributeMaxDynamicSharedMemorySize, SMEM_BYTES);
    cudaFuncSetAttribute(k_kv,   cudaFuncAttributeMaxDynamicSharedMemorySize, SMEM_BYTES);
    cudaFuncSetAttribute(k_out,  cudaFuncAttributeMaxDynamicSharedMemorySize, SMEM_BYTES);

    k_cvt_hi<<<(BN * DD) / 2048, 256>>>(Q, g_q_h);
    k_cvt_hl<<<(BN * DD) / 2048, 256>>>(K, g_k_h, g_k_l);
    k_wprep<<<DD, 256>>>(Wq, Wk);
    k_transV<<<dim3(NN / 32, DD / 32, BB), dim3(32, 8)>>>(V);

    k_phik<<<dim3(BN / 128, 2), 256, SMEM_BYTES>>>(bk);
    k_phiq<<<dim3(BN / 128, 2), 256, SMEM_BYTES>>>(bq);

    k_cs_exp<<<dim3(DD, BB), 256>>>();
    k_rowsum<<<BN / 8, 256>>>();

    k_kv<<<dim3(2, 2, BB * KSPL), 256, SMEM_BYTES>>>();
    k_kvmerge<<<(BB * DD * DD) / 256, 256>>>();

    k_out<<<dim3(BN / 128, 2), 256, SMEM_BYTES>>>(out);
}

// round 12
// speedup vs baseline: 2.5494x; 2.5494x over previous
#include <cuda_runtime.h>
#include <cuda_bf16.h>

#define BB 16
#define NN 4096
#define DD 256
#define BN (BB * NN)
#define EPSF 1e-6f
#define KSPL 4
#define NKV (NN / KSPL)

#define TILE_U16 (128 * 72)                 // one tile: 128 rows x 72 u16 (64 data + 8 pad)
#define SMEM_BYTES (2 * TILE_U16 * 2)       // 36864 B: Ah, Bh

typedef unsigned short u16;
typedef unsigned int u32;

// ---------------- scratch (device globals; allocation-free) ----------------
__device__ u16 g_wqt_h[DD * DD];                      // WqT [e,k] hi
__device__ u16 g_wkt_h[DD * DD];                      // WkT [e,k] hi
__device__ u16 g_phiq_h[(size_t)BN * DD];             // [n,e] hi
__device__ u16 g_phikt_h[(size_t)BN * DD];            // phi_k^T [b,e,n] hi
__device__ u16 g_e_h[(size_t)BN * DD];                // E^T [b,e,n] hi
__device__ float g_vt[(size_t)BN * DD];               // V^T [b,e,n]
__device__ float g_sm[BB * DD];                       // softmax denoms
__device__ float g_rs[BB * NN];                       // phi_q row sums
__device__ float g_kvp[(size_t)KSPL * BB * DD * DD];  // partial KV^T
__device__ u16 g_kvt_h[(size_t)BB * DD * DD];         // KV^T [b,e,d] hi

// ---------------- helpers ----------------
__device__ __forceinline__ float sigmoidf_(float x) { return 1.f / (1.f + __expf(-x)); }

__device__ __forceinline__ u32 smem_u32(const void* p) {
    u32 a;
    asm("{ .reg .u64 t; cvta.to.shared.u64 t, %1; cvt.u32.u64 %0, t; }" : "=r"(a) : "l"(p));
    return a;
}

// store fp32 pair as bf16 hi
__device__ __forceinline__ void store_h(u16* ph, size_t idx, float v0, float v1) {
    __nv_bfloat162 h = __floats2bfloat162_rn(v0, v1);
    *(u32*)(ph + idx) = *(u32*)&h;
}

#define MMA16816(cc, aa, b0, b1)                                               \
    asm volatile("mma.sync.aligned.m16n8k16.row.col.f32.bf16.bf16.f32 "        \
                 "{%0,%1,%2,%3}, {%4,%5,%6,%7}, {%8,%9}, {%0,%1,%2,%3};"       \
                 : "+f"((cc)[0]), "+f"((cc)[1]), "+f"((cc)[2]), "+f"((cc)[3])  \
                 : "r"((aa)[0]), "r"((aa)[1]), "r"((aa)[2]), "r"((aa)[3]),     \
                   "r"(b0), "r"(b1))

#define LDSM4(rr, addr)                                                        \
    asm volatile("ldmatrix.sync.aligned.m8n8.x4.shared.b16 {%0,%1,%2,%3}, [%4];" \
                 : "=r"((rr)[0]), "=r"((rr)[1]), "=r"((rr)[2]), "=r"((rr)[3])  \
                 : "r"(addr))

#define MMAALL(AF, BF)                                                         \
    _Pragma("unroll") for (int mi = 0; mi < 4; mi++)                           \
    _Pragma("unroll") for (int nj = 0; nj < 4; nj++)                           \
        MMA16816(c[mi][nj], AF[mi], BF[nj >> 1][nj & 1], BF[nj >> 1][(nj & 1) + 2]);

// ---- staging: 128 rows x 32 k into half of a 72-u16-stride tile ----
// bf16 copy (hi plane)
__device__ __forceinline__ void stage_b16c_hi(const u16* __restrict__ gh,
                                              size_t ldg, u16* sh,
                                              int tid, int colbase) {
    int row = tid >> 1, half = tid & 1;
    const u16* grh = gh + (size_t)row * ldg + half * 16;
    u16* drh = sh + row * 72 + colbase + half * 16;
#pragma unroll
    for (int q = 0; q < 2; q++) {
        uint4 h = *(const uint4*)(grh + q * 8);
        *(uint4*)(drh + q * 8) = h;
    }
}

// f32 -> bf16 hi plane
__device__ __forceinline__ void stage_f32c_hi(const float* __restrict__ g,
                                              size_t ldg, u16* sh,
                                              int tid, int colbase) {
    int row = tid >> 1, half = tid & 1;
    const float4* p = (const float4*)(g + (size_t)row * ldg + half * 16);
    u16* drh = sh + row * 72 + colbase + half * 16;
#pragma unroll
    for (int j = 0; j < 4; j++) {
        float4 v = p[j];
        __nv_bfloat162 h0 = __floats2bfloat162_rn(v.x, v.y);
        __nv_bfloat162 h1 = __floats2bfloat162_rn(v.z, v.w);
        *(uint2*)(drh + j * 4) = make_uint2(*(u32*)&h0, *(u32*)&h1);
    }
}

// ---------------------------------------------------------------------------
// GEMM core: 128x128 block tile, 8 warps (2m x 4n), warp tile 64x32,
// K staged by 64, single-plane bf16, fp32 accum. Dynamic smem 36KB.
// ---------------------------------------------------------------------------
#define GEMM_CORE(KTOT, ...)                                                   \
    extern __shared__ u16 smemu[];                                             \
    u16* sAh = smemu;                                                          \
    u16* sBh = smemu + TILE_U16;                                               \
    float c[4][4][4];                                                          \
    _Pragma("unroll") for (int i_ = 0; i_ < 4; i_++)                           \
    _Pragma("unroll") for (int j_ = 0; j_ < 4; j_++)                           \
    _Pragma("unroll") for (int r_ = 0; r_ < 4; r_++) c[i_][j_][r_] = 0.f;      \
    const int lane = tid & 31, widx = tid >> 5;                                \
    const int wm = widx >> 2, wn = widx & 3;                                   \
    const u32 frow = (u32)(lane & 15) * 144 + (u32)(lane >> 4) * 16;           \
    const u32 uAh = smem_u32(sAh) + wm * 64 * 144 + frow;                      \
    const u32 uBh = smem_u32(sBh) + wn * 32 * 144 + frow;                      \
    for (int kt = 0; kt < (KTOT); kt += 64) {                                  \
        __syncthreads();                                                       \
        { __VA_ARGS__ }                                                        \
        __syncthreads();                                                       \
        _Pragma("unroll")                                                      \
        for (int s = 0; s < 4; s++) {                                          \
            u32 ah[4][4], bb[2][4];                                            \
            LDSM4(bb[0], uBh + s * 32);                                        \
            LDSM4(bb[1], uBh + 16 * 144 + s * 32);                             \
            _Pragma("unroll") for (int mi = 0; mi < 4; mi++)                   \
                LDSM4(ah[mi], uAh + mi * 16 * 144 + s * 32);                   \
            MMAALL(ah, bb)                                                     \
        }                                                                      \
    }

// epilogue loop; variadic so bodies may contain top-level commas
#define EPILOOP(...)                                                           \
    _Pragma("unroll") for (int mi = 0; mi < 4; mi++)                           \
    _Pragma("unroll") for (int nj = 0; nj < 4; nj++) {                         \
        int r0 = wm * 64 + mi * 16 + (lane >> 2);                              \
        int cc0 = wn * 32 + nj * 8 + ((lane & 3) << 1);                        \
        __VA_ARGS__                                                            \
    }

// ---------------------------------------------------------------------------
// prep: WT hi [e,k] from W [k,e]
// ---------------------------------------------------------------------------
__global__ void k_wprep(const float* __restrict__ Wq, const float* __restrict__ Wk)
{
    int e = blockIdx.x, k = threadIdx.x;
    __nv_bfloat16 qh = __float2bfloat16(Wq[(size_t)k * DD + e]);
    __nv_bfloat16 kh = __float2bfloat16(Wk[(size_t)k * DD + e]);
    g_wqt_h[e * DD + k] = *(u16*)&qh;
    g_wkt_h[e * DD + k] = *(u16*)&kh;
}

// V transpose: V[b,n,e] -> V^T[b,e,n]
__global__ void k_transV(const float* __restrict__ V)
{
    __shared__ float t[32][33];
    int n0 = blockIdx.x * 32, e0 = blockIdx.y * 32, b = blockIdx.z;
    int tx = threadIdx.x, ty = threadIdx.y;
#pragma unroll
    for (int i = 0; i < 4; i++)
        t[ty + 8 * i][tx] = V[((size_t)b * NN + n0 + ty + 8 * i) * DD + e0 + tx];
    __syncthreads();
#pragma unroll
    for (int i = 0; i < 4; i++)
        g_vt[((size_t)b * DD + e0 + ty + 8 * i) * NN + n0 + tx] = t[tx][ty + 8 * i];
}

// ---------------------------------------------------------------------------
// phi_q[n,e] = sigmoid(Q@Wq + bq).  A=Q[n,k] hi, B=WqT[e,k] hi
// ---------------------------------------------------------------------------
__global__ void __launch_bounds__(256, 2)
k_phiq(const float* __restrict__ Q, const float* __restrict__ bq)
{
    const int tid = threadIdx.x;
    const int m0 = blockIdx.x * 128;   // global n
    const int e0 = blockIdx.y * 128;

    GEMM_CORE(DD,
        stage_f32c_hi(Q + (size_t)m0 * DD + kt, DD, sAh, tid, 0);
        stage_f32c_hi(Q + (size_t)m0 * DD + kt + 32, DD, sAh, tid, 32);
        stage_b16c_hi(g_wqt_h + (size_t)e0 * DD + kt, DD, sBh, tid, 0);
        stage_b16c_hi(g_wqt_h + (size_t)e0 * DD + kt + 32, DD, sBh, tid, 32);
    )

    EPILOOP(
        int e = e0 + cc0;
        float2 bqe = *(const float2*)(bq + e);
        int n0g = m0 + r0;
        store_h(g_phiq_h, (size_t)n0g * DD + e,
                sigmoidf_(c[mi][nj][0] + bqe.x), sigmoidf_(c[mi][nj][1] + bqe.y));
        store_h(g_phiq_h, (size_t)(n0g + 8) * DD + e,
                sigmoidf_(c[mi][nj][2] + bqe.x), sigmoidf_(c[mi][nj][3] + bqe.y));
    )
}

// ---------------------------------------------------------------------------
// phi_k^T[b,e,n] = sigmoid(K@Wk + bk)^T.  A=WkT[e,k] hi, B=K[n,k] hi
// ---------------------------------------------------------------------------
__global__ void __launch_bounds__(256, 2)
k_phik(const float* __restrict__ Kin, const float* __restrict__ bk)
{
    const int tid = threadIdx.x;
    const int n0 = blockIdx.x * 128;   // global n
    const int m0e = blockIdx.y * 128;  // e

    GEMM_CORE(DD,
        stage_b16c_hi(g_wkt_h + (size_t)m0e * DD + kt, DD, sAh, tid, 0);
        stage_b16c_hi(g_wkt_h + (size_t)m0e * DD + kt + 32, DD, sAh, tid, 32);
        stage_f32c_hi(Kin + (size_t)n0 * DD + kt, DD, sBh, tid, 0);
        stage_f32c_hi(Kin + (size_t)n0 * DD + kt + 32, DD, sBh, tid, 32);
    )

    EPILOOP(
        int er = m0e + r0;
        int gn = n0 + cc0;
        int b = gn >> 12;
        int nl = gn & (NN - 1);
        float b0 = bk[er];
        float b1 = bk[er + 8];
        store_h(g_phikt_h, ((size_t)b * DD + er) * NN + nl,
                sigmoidf_(c[mi][nj][0] + b0), sigmoidf_(c[mi][nj][1] + b0));
        store_h(g_phikt_h, ((size_t)b * DD + er + 8) * NN + nl,
                sigmoidf_(c[mi][nj][2] + b1), sigmoidf_(c[mi][nj][3] + b1));
    )
}

// ---------------------------------------------------------------------------
// per (b,e): colsum(phi_k) -> inv; E = exp(phi_k*V*inv); rowsum(E) -> sm
// ---------------------------------------------------------------------------
__global__ void __launch_bounds__(256) k_cs_exp()
{
    __shared__ float red[256];
    const int e = blockIdx.x, b = blockIdx.y, tid = threadIdx.x;
    const size_t base = ((size_t)b * DD + e) * NN;
    const u16* ph = g_phikt_h + base;
    const float* vt = g_vt + base;

    float pkx[8], pky[8];
    float s = 0.f;
#pragma unroll
    for (int i = 0; i < 8; i++) {
        int n = i * 512 + tid * 2;
        u32 hp = *(const u32*)(ph + n);
        float2 hf = __bfloat1622float2(*(__nv_bfloat162*)&hp);
        pkx[i] = hf.x;
        pky[i] = hf.y;
        s += pkx[i] + pky[i];
    }
    red[tid] = s; __syncthreads();
    for (int o = 128; o > 0; o >>= 1) { if (tid < o) red[tid] += red[tid + o]; __syncthreads(); }
    const float inv = 1.f / (red[0] + EPSF);
    __syncthreads();

    float s2 = 0.f;
#pragma unroll
    for (int i = 0; i < 8; i++) {
        int n = i * 512 + tid * 2;
        float2 vv = *(const float2*)(vt + n);
        float E0 = __expf(pkx[i] * vv.x * inv);
        float E1 = __expf(pky[i] * vv.y * inv);
        store_h(g_e_h, base + n, E0, E1);
        s2 += E0 + E1;
    }
    red[tid] = s2; __syncthreads();
    for (int o = 128; o > 0; o >>= 1) { if (tid < o) red[tid] += red[tid + o]; __syncthreads(); }
    if (tid == 0) g_sm[b * DD + e] = red[0];
}

// row sums of phi_q over d (warp per row)
__global__ void __launch_bounds__(256) k_rowsum()
{
    const int row = blockIdx.x * 8 + (threadIdx.x >> 5);
    const int lane = threadIdx.x & 31;
    const u16* ph = g_phiq_h + (size_t)row * DD;
    float s = 0.f;
#pragma unroll
    for (int i = 0; i < 4; i++) {
        int j2 = (lane + 32 * i) * 2;
        u32 hp = *(const u32*)(ph + j2);
        float2 hf = __bfloat1622float2(*(__nv_bfloat162*)&hp);
        s += hf.x + hf.y;
    }
#pragma unroll
    for (int o = 16; o > 0; o >>= 1) s += __shfl_down_sync(0xffffffffu, s, o);
    if (lane == 0) g_rs[row] = s;
}

// ---------------------------------------------------------------------------
// KV partial: kvp[spl,b,e,d] = sum_{n in slice} E^T[e,n]*phi_k^T[d,n]
// ---------------------------------------------------------------------------
__global__ void __launch_bounds__(256, 2) k_kv()
{
    const int tid = threadIdx.x;
    const int d0 = blockIdx.x * 128;
    const int e0 = blockIdx.y * 128;
    const int b = blockIdx.z >> 2;
    const int spl = blockIdx.z & 3;
    const size_t abase = ((size_t)b * DD + e0) * NN + spl * NKV;
    const size_t bbase = ((size_t)b * DD + d0) * NN + spl * NKV;

    GEMM_CORE(NKV,
        stage_b16c_hi(g_e_h + abase + kt, NN, sAh, tid, 0);
        stage_b16c_hi(g_e_h + abase + kt + 32, NN, sAh, tid, 32);
        stage_b16c_hi(g_phikt_h + bbase + kt, NN, sBh, tid, 0);
        stage_b16c_hi(g_phikt_h + bbase + kt + 32, NN, sBh, tid, 32);
    )

    float* dst = g_kvp + (size_t)(spl * BB + b) * DD * DD;
    EPILOOP(
        int e = e0 + r0;
        int d = d0 + cc0;
        *(float2*)(dst + (size_t)e * DD + d) = make_float2(c[mi][nj][0], c[mi][nj][1]);
        *(float2*)(dst + (size_t)(e + 8) * DD + d) = make_float2(c[mi][nj][2], c[mi][nj][3]);
    )
}

// merge split-K, divide by sm[b,e], store KV^T [b,e,d] hi
__global__ void __launch_bounds__(256) k_kvmerge()
{
    const size_t idx2 = ((size_t)blockIdx.x * 256 + threadIdx.x) * 2;
    const size_t S = (size_t)BB * DD * DD;
    const int e = (int)((idx2 >> 8) & 255);
    const int b = (int)(idx2 >> 16);
    float inv = 1.f / g_sm[b * DD + e];
    float2 s0 = *(const float2*)(g_kvp + idx2);
    float2 s1 = *(const float2*)(g_kvp + S + idx2);
    float2 s2 = *(const float2*)(g_kvp + 2 * S + idx2);
    float2 s3 = *(const float2*)(g_kvp + 3 * S + idx2);
    float v0 = (s0.x + s1.x + s2.x + s3.x) * inv;
    float v1 = (s0.y + s1.y + s2.y + s3.y) * inv;
    store_h(g_kvt_h, idx2, v0, v1);
}

// ---------------------------------------------------------------------------
// out[n,e] = sigmoid(rs)/(rs+eps) * sum_d phi_q[n,d]*KV^T[e,d]
// ---------------------------------------------------------------------------
__global__ void __launch_bounds__(256, 2) k_out(float* __restrict__ out)
{
    const int tid = threadIdx.x;
    const int m0 = blockIdx.x * 128;   // global n
    const int e0 = blockIdx.y * 128;
    const int b = m0 >> 12;
    const size_t abase = (size_t)m0 * DD;
    const size_t bbase = ((size_t)b * DD + e0) * DD;

    GEMM_CORE(DD,
        stage_b16c_hi(g_phiq_h + abase + kt, DD, sAh, tid, 0);
        stage_b16c_hi(g_phiq_h + abase + kt + 32, DD, sAh, tid, 32);
        stage_b16c_hi(g_kvt_h + bbase + kt, DD, sBh, tid, 0);
        stage_b16c_hi(g_kvt_h + bbase + kt + 32, DD, sBh, tid, 32);
    )

    EPILOOP(
        int ng = m0 + r0;
        int e = e0 + cc0;
        float rs0 = g_rs[ng];
        float rs1 = g_rs[ng + 8];
        float s0 = sigmoidf_(rs0) / (rs0 + EPSF);
        float s1 = sigmoidf_(rs1) / (rs1 + EPSF);
        *(float2*)(out + (size_t)ng * DD + e) =
            make_float2(c[mi][nj][0] * s0, c[mi][nj][1] * s0);
        *(float2*)(out + (size_t)(ng + 8) * DD + e) =
            make_float2(c[mi][nj][2] * s1, c[mi][nj][3] * s1);
    )
}

// ---------------------------------------------------------------------------
extern "C" void kernel_launch(void* const* d_in, const int* in_sizes, int n_in,
                              void* d_out, int out_size)
{
    const float* Q  = (const float*)d_in[0];
    const float* K  = (const float*)d_in[1];
    const float* V  = (const float*)d_in[2];
    const float* Wq = (const float*)d_in[3];
    const float* bq = (const float*)d_in[4];
    const float* Wk = (const float*)d_in[5];
    const float* bk = (const float*)d_in[6];
    float* out = (float*)d_out;

    k_wprep<<<DD, 256>>>(Wq, Wk);
    k_transV<<<dim3(NN / 32, DD / 32, BB), dim3(32, 8)>>>(V);

    k_phik<<<dim3(BN / 128, 2), 256, SMEM_BYTES>>>(K, bk);
    k_phiq<<<dim3(BN / 128, 2), 256, SMEM_BYTES>>>(Q, bq);

    k_cs_exp<<<dim3(DD, BB), 256>>>();
    k_rowsum<<<BN / 8, 256>>>();

    k_kv<<<dim3(2, 2, BB * KSPL), 256, SMEM_BYTES>>>();
    k_kvmerge<<<(BB * DD * DD) / 512, 256>>>();

    k_out<<<dim3(BN / 128, 2), 256, SMEM_BYTES>>>(out);
}